// round 12
// baseline (speedup 1.0000x reference)
#include <cuda_runtime.h>
#include <cuda_bf16.h>
#include <cstdint>

#define BB 256
#define SS 512
#define DD 1024
#define TT 17
#define EST 20   // padded eem row stride (16B-aligned rows)

// ---------------- device scratch (no allocations allowed) ----------------
__device__ float g_eem[(size_t)BB * SS * EST];  // exp(em - rowmax), 10.5 MB
__device__ float g_part_score[1024];            // per-CTA numerator partials
__device__ float g_part_msum[1024];             // per-CTA sum of masked row-maxes
__device__ int   g_part_mcnt[1024];             // per-CTA mask counts
__device__ float g_denom[BB];                   // log partition minus msum offset

// ---------------- smem layout (bytes) ----------------
#define SM_B    0                       // W bf16: 24 n-rows x 1024 k = 48 KB
#define SM_A    49152                   // 4 warps x 1 buf x 4 KB = 16 KB
#define SM_D    SM_A                    // D reuse: 128 x 26 fp32 = 13312 B
#define SM_RED  (SM_A + 16384)          // 65536
#define SM_TOT  (SM_RED + 64)           // 65600

__device__ __forceinline__ uint2 cvt_f4_bf16x4(float4 f) {
    uint2 r;
    // low 16 bits = earlier k element
    asm("cvt.rn.bf16x2.f32 %0, %1, %2;" : "=r"(r.x) : "f"(f.y), "f"(f.x));
    asm("cvt.rn.bf16x2.f32 %0, %1, %2;" : "=r"(r.y) : "f"(f.w), "f"(f.z));
    return r;
}

__device__ __forceinline__ void mma16816(float* d, const uint32_t* a,
                                         const uint32_t* b) {
    asm volatile(
        "mma.sync.aligned.m16n8k16.row.col.f32.bf16.bf16.f32 "
        "{%0,%1,%2,%3}, {%4,%5,%6,%7}, {%8,%9}, {%0,%1,%2,%3};"
        : "+f"(d[0]), "+f"(d[1]), "+f"(d[2]), "+f"(d[3])
        : "r"(a[0]), "r"(a[1]), "r"(a[2]), "r"(a[3]), "r"(b[0]), "r"(b[1]));
}

// ============================================================
// Kernel 1: HMMA emissions GEMM + eem/rowmax + numerator partials
//   1024 CTAs x 128 threads, 3 CTAs/SM (12 warps) for DRAM latency cover.
//   (unchanged from R11 measured-best)
// ============================================================
__global__ void __launch_bounds__(128, 3)
emis_kernel(const float* __restrict__ data, const int* __restrict__ labels,
            const int* __restrict__ mask, const float* __restrict__ W,
            const float* __restrict__ bias, const float* __restrict__ start,
            const float* __restrict__ trans)
{
    extern __shared__ char smem[];
    const int tid = threadIdx.x;
    const int blk = blockIdx.x;
    const int w   = tid >> 5;
    const int l   = tid & 31;

    // ---- stage B = W as bf16 [24 n x 1024 k], swizzled ----
    for (int i = tid; i < 896; i += 128)
        reinterpret_cast<uint4*>(smem + SM_B + 17 * 2048)[i] =
            make_uint4(0u, 0u, 0u, 0u);
    const float4* W4 = reinterpret_cast<const float4*>(W);
    for (int i = tid; i < TT * DD / 4; i += 128) {
        int n = i >> 8, k4 = i & 255;
        uint32_t off = (uint32_t)(n * 2048 + ((k4 * 8) ^ ((n & 7) << 4)));
        *reinterpret_cast<uint2*>(smem + SM_B + off) =
            cvt_f4_bf16x4(__ldg(W4 + i));
    }

    // ---- A staging geometry (warp-private, single 4 KB buffer) ----
    const int lr8 = l >> 4;
    const int q   = l & 15;
    const float4* dq = reinterpret_cast<const float4*>(data);
    const long g0 = (long)(blk * 128 + w * 32 + lr8) * 256 + q;
    char* buf = smem + SM_A + w * 4096;

    float4 raw[16];
    #pragma unroll
    for (int i = 0; i < 16; i++)
        raw[i] = __ldg(dq + g0 + (long)i * 512);

    __syncthreads();   // B ready

    float acc[2][3][4];
    #pragma unroll
    for (int mt = 0; mt < 2; mt++)
        #pragma unroll
        for (int nt = 0; nt < 3; nt++)
            #pragma unroll
            for (int x = 0; x < 4; x++) acc[mt][nt][x] = 0.0f;

    const int rk = l >> 2;
    const int cx = (l & 3) * 4;
    const uint32_t keysh = (uint32_t)rk << 4;
    char* sB = smem + SM_B;

    #pragma unroll 1
    for (int c = 0; c < 16; c++) {
        #pragma unroll
        for (int i = 0; i < 16; i++) {
            uint2 pk = cvt_f4_bf16x4(raw[i]);
            *reinterpret_cast<uint2*>(
                buf + (i * 2 + lr8) * 128 +
                ((q * 8) ^ (((i & 3) * 2 + lr8) << 4))) = pk;
        }
        __syncwarp();

        if (c < 15) {
            #pragma unroll
            for (int i = 0; i < 16; i++)
                raw[i] = __ldg(dq + g0 + (long)i * 512 + (c + 1) * 16);
        }

        #pragma unroll
        for (int ks = 0; ks < 4; ks++) {
            const uint32_t a0o = (uint32_t)(rk * 128) + (((uint32_t)(ks * 32 + cx)) ^ keysh);
            uint32_t aA[2][4];
            #pragma unroll
            for (int mt = 0; mt < 2; mt++) {
                char* bm = buf + mt * 2048;
                aA[mt][0] = *reinterpret_cast<uint32_t*>(bm + a0o);
                aA[mt][1] = *reinterpret_cast<uint32_t*>(bm + a0o + 1024);
                aA[mt][2] = *reinterpret_cast<uint32_t*>(bm + (a0o ^ 16));
                aA[mt][3] = *reinterpret_cast<uint32_t*>(bm + (a0o ^ 16) + 1024);
            }
            #pragma unroll
            for (int nt = 0; nt < 3; nt++) {
                const uint32_t b0o = (uint32_t)((nt * 8 + rk) * 2048) +
                    (((uint32_t)(c * 128 + ks * 32 + cx)) ^ keysh);
                uint32_t bb[2];
                bb[0] = *reinterpret_cast<uint32_t*>(sB + b0o);
                bb[1] = *reinterpret_cast<uint32_t*>(sB + (b0o ^ 16));
                mma16816(acc[0][nt], aA[0], bb);
                mma16816(acc[1][nt], aA[1], bb);
            }
        }
        __syncwarp();
    }

    // ---- D -> smem (stride 26 floats), then per-thread row epilogue ----
    __syncthreads();
    float* sD = reinterpret_cast<float*>(smem + SM_D);
    #pragma unroll
    for (int mt = 0; mt < 2; mt++)
        #pragma unroll
        for (int nt = 0; nt < 3; nt++) {
            int r  = w * 32 + mt * 16 + rk;
            int cb = nt * 8 + (l & 3) * 2;
            *reinterpret_cast<float2*>(sD + r * 26 + cb) =
                make_float2(acc[mt][nt][0], acc[mt][nt][1]);
            *reinterpret_cast<float2*>(sD + (r + 8) * 26 + cb) =
                make_float2(acc[mt][nt][2], acc[mt][nt][3]);
        }
    __syncthreads();

    const int row = blk * 128 + tid;
    const int s   = row & (SS - 1);

    float emv[TT];
    float m = -1e30f;
    #pragma unroll
    for (int t = 0; t < TT; t++) {
        emv[t] = sD[tid * 26 + t] + __ldg(bias + t);
        m = fmaxf(m, emv[t]);
    }
    float e[TT];
    #pragma unroll
    for (int t = 0; t < TT; t++) e[t] = __expf(emv[t] - m);

    float4* o4 = reinterpret_cast<float4*>(g_eem + (size_t)row * EST);
    o4[0] = make_float4(e[0],  e[1],  e[2],  e[3]);
    o4[1] = make_float4(e[4],  e[5],  e[6],  e[7]);
    o4[2] = make_float4(e[8],  e[9],  e[10], e[11]);
    o4[3] = make_float4(e[12], e[13], e[14], e[15]);
    o4[4] = make_float4(e[16], 0.0f,  0.0f,  0.0f);

    int lab = __ldg(labels + row);
    float em_lab = 0.0f;
    #pragma unroll
    for (int t = 0; t < TT; t++) em_lab = (lab == t) ? emv[t] : em_lab;

    float mk = (__ldg(mask + row) != 0) ? 1.0f : 0.0f;
    float contrib;
    if (s == 0) {
        contrib = __ldg(start + lab) + em_lab;
    } else {
        int prev = __ldg(labels + row - 1);
        contrib = mk * (__ldg(trans + prev * TT + lab) + em_lab);
    }
    float msum_t = mk * m;
    int   mcnt_t = (mk > 0.0f) ? 1 : 0;

    const unsigned FULL = 0xffffffffu;
    #pragma unroll
    for (int off = 16; off; off >>= 1) {
        contrib += __shfl_xor_sync(FULL, contrib, off);
        msum_t  += __shfl_xor_sync(FULL, msum_t, off);
        mcnt_t  += __shfl_xor_sync(FULL, mcnt_t, off);
    }
    float* red = reinterpret_cast<float*>(smem + SM_RED);
    if (l == 0) {
        red[w]     = contrib;
        red[4 + w] = msum_t;
        reinterpret_cast<int*>(red)[8 + w] = mcnt_t;
    }
    __syncthreads();
    if (tid == 0) {
        float sc = 0.0f, sm = 0.0f; int cn = 0;
        #pragma unroll
        for (int ww = 0; ww < 4; ww++) {
            sc += red[ww];
            sm += red[4 + ww];
            cn += reinterpret_cast<int*>(red)[8 + ww];
        }
        g_part_score[blk] = sc;
        g_part_msum[blk]  = sm;
        g_part_mcnt[blk]  = cn;
    }
}

// ============================================================
// Kernel 2: CRF forward recurrence — 2 independent chains per warp
//   128 blocks x 32 threads; batches (2w, 2w+1) interleaved for ILP.
// ============================================================
__global__ void __launch_bounds__(32)
crf_kernel(const float* __restrict__ trans, const float* __restrict__ start,
           const float* __restrict__ endt, const int* __restrict__ mask)
{
    const unsigned FULL = 0xffffffffu;
    const int j = threadIdx.x;
    const bool act = (j < TT);
    const int b0 = blockIdx.x * 2;

    float Ecol[TT];
    #pragma unroll
    for (int i = 0; i < TT; i++)
        Ecol[i] = act ? __expf(__ldg(trans + i * TT + j)) : 0.0f;
    float eend = act ? __expf(__ldg(endt + j)) : 0.0f;
    float est  = act ? __expf(__ldg(start + j)) : 0.0f;

    const float* eb0 = g_eem + (size_t)b0 * (SS * EST);
    const float* eb1 = eb0 + (size_t)SS * EST;
    const int4* mb0 = reinterpret_cast<const int4*>(mask + b0 * SS);
    const int4* mb1 = reinterpret_cast<const int4*>(mask + (b0 + 1) * SS);

    float bufA[2][8], bufB[2][8];
    int   mA[2][8],  mB[2][8];

    #pragma unroll
    for (int d = 0; d < 8; d++) {
        bufA[0][d] = act ? __ldg(eb0 + d * EST + j) : 0.0f;
        bufA[1][d] = act ? __ldg(eb1 + d * EST + j) : 0.0f;
    }
    {
        int4 a0 = __ldg(mb0 + 0), c0 = __ldg(mb0 + 1);
        int4 a1 = __ldg(mb1 + 0), c1 = __ldg(mb1 + 1);
        mA[0][0]=a0.x; mA[0][1]=a0.y; mA[0][2]=a0.z; mA[0][3]=a0.w;
        mA[0][4]=c0.x; mA[0][5]=c0.y; mA[0][6]=c0.z; mA[0][7]=c0.w;
        mA[1][0]=a1.x; mA[1][1]=a1.y; mA[1][2]=a1.z; mA[1][3]=a1.w;
        mA[1][4]=c1.x; mA[1][5]=c1.y; mA[1][6]=c1.z; mA[1][7]=c1.w;
    }

    float p[2], C[2], r[2], sc[2], lr[2];
    p[0] = bufA[0][0] * est;
    p[1] = bufA[1][0] * est;
    #pragma unroll
    for (int u = 0; u < 2; u++) {
        C[u]  = 0.0f;
        r[u]  = __shfl_sync(FULL, p[u], 0);
        sc[u] = __fdividef(1.0f, r[u]);
        lr[u] = __logf(r[u]);
    }

    // fused step for both chains: independent -> ILP fills latency shadow
    auto step2 = [&](float e0, int m0, float e1, int m1) {
        float a0[4] = {0.f, 0.f, 0.f, 0.f};
        float a1[4] = {0.f, 0.f, 0.f, 0.f};
        #pragma unroll
        for (int i = 0; i < TT; i++) {
            float s0 = __shfl_sync(FULL, p[0], i);
            float s1 = __shfl_sync(FULL, p[1], i);
            a0[i & 3] = fmaf(s0, Ecol[i], a0[i & 3]);
            a1[i & 3] = fmaf(s1, Ecol[i], a1[i & 3]);
        }
        float q0 = (a0[0] + a0[1]) + (a0[2] + a0[3]);
        float q1 = (a1[0] + a1[1]) + (a1[2] + a1[3]);
        if (m0 != 0) {   // warp-uniform
            p[0] = q0 * (e0 * sc[0]);
            C[0] += lr[0];
            r[0]  = __shfl_sync(FULL, p[0], 0);
            sc[0] = __fdividef(1.0f, r[0]);
            lr[0] = __logf(r[0]);
        }
        if (m1 != 0) {
            p[1] = q1 * (e1 * sc[1]);
            C[1] += lr[1];
            r[1]  = __shfl_sync(FULL, p[1], 0);
            sc[1] = __fdividef(1.0f, r[1]);
            lr[1] = __logf(r[1]);
        }
    };

    #define PREFETCH(cidx, BUF, MARR)                                           \
        do {                                                                     \
            _Pragma("unroll")                                                    \
            for (int d = 0; d < 8; d++) {                                        \
                BUF[0][d] = act ? __ldg(eb0 + ((cidx) * 8 + d) * EST + j) : 0.f; \
                BUF[1][d] = act ? __ldg(eb1 + ((cidx) * 8 + d) * EST + j) : 0.f; \
            }                                                                    \
            int4 _a0 = __ldg(mb0 + 2 * (cidx)), _c0 = __ldg(mb0 + 2 * (cidx) + 1);\
            int4 _a1 = __ldg(mb1 + 2 * (cidx)), _c1 = __ldg(mb1 + 2 * (cidx) + 1);\
            MARR[0][0]=_a0.x; MARR[0][1]=_a0.y; MARR[0][2]=_a0.z; MARR[0][3]=_a0.w;\
            MARR[0][4]=_c0.x; MARR[0][5]=_c0.y; MARR[0][6]=_c0.z; MARR[0][7]=_c0.w;\
            MARR[1][0]=_a1.x; MARR[1][1]=_a1.y; MARR[1][2]=_a1.z; MARR[1][3]=_a1.w;\
            MARR[1][4]=_c1.x; MARR[1][5]=_c1.y; MARR[1][6]=_c1.z; MARR[1][7]=_c1.w;\
        } while (0)

    #define PROCESS(BUF, MARR)                                                   \
        do {                                                                      \
            _Pragma("unroll")                                                     \
            for (int d = 0; d < 8; d++)                                           \
                step2(BUF[0][d], MARR[0][d], BUF[1][d], MARR[1][d]);              \
        } while (0)

    // prefetch chunk 1, process chunk 0 steps 1..7
    PREFETCH(1, bufB, mB);
    #pragma unroll
    for (int d = 1; d < 8; d++)
        step2(bufA[0][d], mA[0][d], bufA[1][d], mA[1][d]);

    // main: chunks 1..62 double-buffered, chunk 63 tail
    for (int cc = 1; cc < 63; cc += 2) {
        PREFETCH(cc + 1, bufA, mA);
        PROCESS(bufB, mB);
        PREFETCH(cc + 2, bufB, mB);
        PROCESS(bufA, mA);
    }
    PROCESS(bufB, mB);

    // denom (minus msum offset) = C + log(sum_j p_j * exp(end_j))
    float t0 = p[0] * eend;
    float t1 = p[1] * eend;
    #pragma unroll
    for (int off = 16; off; off >>= 1) {
        t0 += __shfl_xor_sync(FULL, t0, off);
        t1 += __shfl_xor_sync(FULL, t1, off);
    }
    if (j == 0) {
        g_denom[b0]     = C[0] + __logf(t0);
        g_denom[b0 + 1] = C[1] + __logf(t1);
    }

    #undef PREFETCH
    #undef PROCESS
}

// ============================================================
// Kernel 3: finalize  out = -mean(score - denom)
// ============================================================
__global__ void __launch_bounds__(256)
fin_kernel(const int* __restrict__ labels, const float* __restrict__ endt,
           float* __restrict__ out)
{
    __shared__ float sred[256];
    int b = threadIdx.x;
    int cnt = 0;
    float psc = 0.0f, pms = 0.0f;
    #pragma unroll
    for (int k = 0; k < 4; k++) {
        cnt += g_part_mcnt[4 * b + k];
        psc += g_part_score[4 * b + k];
        pms += g_part_msum[4 * b + k];
    }
    int lt = __ldg(labels + b * SS + (cnt - 1));
    float score = psc + __ldg(endt + lt);
    float denom = g_denom[b] + pms;
    sred[b] = score - denom;
    __syncthreads();
    #pragma unroll
    for (int off = 128; off; off >>= 1) {
        if (b < off) sred[b] += sred[b + off];
        __syncthreads();
    }
    if (b == 0) out[0] = -sred[0] * (1.0f / BB);
}

// ============================================================
extern "C" void kernel_launch(void* const* d_in, const int* in_sizes, int n_in,
                              void* d_out, int out_size)
{
    const float* data   = (const float*)d_in[0];
    const int*   labels = (const int*)d_in[1];
    const int*   mask   = (const int*)d_in[2];
    const float* W      = (const float*)d_in[3];
    const float* bias   = (const float*)d_in[4];
    const float* start  = (const float*)d_in[5];
    const float* endt   = (const float*)d_in[6];
    const float* trans  = (const float*)d_in[7];

    cudaFuncSetAttribute(emis_kernel,
                         cudaFuncAttributeMaxDynamicSharedMemorySize, SM_TOT);

    emis_kernel<<<1024, 128, SM_TOT>>>(data, labels, mask, W, bias, start, trans);
    crf_kernel<<<BB / 2, 32>>>(trans, start, endt, mask);
    fin_kernel<<<1, 256>>>(labels, endt, (float*)d_out);
}

// round 13
// speedup vs baseline: 1.5459x; 1.5459x over previous
#include <cuda_runtime.h>
#include <cuda_bf16.h>
#include <cstdint>

#define BB 256
#define SS 512
#define DD 1024
#define TT 17
#define EST 20   // padded eem row stride (16B-aligned rows)

// ---------------- device scratch (no allocations allowed) ----------------
__device__ float g_eem[(size_t)BB * SS * EST];  // exp(em - rowmax), 10.5 MB
__device__ float g_part_score[1024];            // per-CTA numerator partials
__device__ float g_part_msum[1024];             // per-CTA sum of masked row-maxes
__device__ int   g_part_mcnt[1024];             // per-CTA mask counts
__device__ float g_denom[BB];                   // log partition minus msum offset

// ---------------- smem layout (bytes) ----------------
#define SM_B    0                       // W bf16: 24 n-rows x 1024 k = 48 KB
#define SM_A    49152                   // 4 warps x 1 buf x 4 KB = 16 KB
#define SM_D    SM_A                    // D reuse: 128 x 26 fp32 = 13312 B
#define SM_RED  (SM_A + 16384)          // 65536
#define SM_TOT  (SM_RED + 64)           // 65600

__device__ __forceinline__ uint2 cvt_f4_bf16x4(float4 f) {
    uint2 r;
    // low 16 bits = earlier k element
    asm("cvt.rn.bf16x2.f32 %0, %1, %2;" : "=r"(r.x) : "f"(f.y), "f"(f.x));
    asm("cvt.rn.bf16x2.f32 %0, %1, %2;" : "=r"(r.y) : "f"(f.w), "f"(f.z));
    return r;
}

__device__ __forceinline__ void mma16816(float* d, const uint32_t* a,
                                         const uint32_t* b) {
    asm volatile(
        "mma.sync.aligned.m16n8k16.row.col.f32.bf16.bf16.f32 "
        "{%0,%1,%2,%3}, {%4,%5,%6,%7}, {%8,%9}, {%0,%1,%2,%3};"
        : "+f"(d[0]), "+f"(d[1]), "+f"(d[2]), "+f"(d[3])
        : "r"(a[0]), "r"(a[1]), "r"(a[2]), "r"(a[3]), "r"(b[0]), "r"(b[1]));
}

// ============================================================
// Kernel 1: HMMA emissions GEMM + eem/rowmax + numerator partials
//   1024 CTAs x 128 threads, 3 CTAs/SM (unchanged, R11 measured-best)
// ============================================================
__global__ void __launch_bounds__(128, 3)
emis_kernel(const float* __restrict__ data, const int* __restrict__ labels,
            const int* __restrict__ mask, const float* __restrict__ W,
            const float* __restrict__ bias, const float* __restrict__ start,
            const float* __restrict__ trans)
{
    extern __shared__ char smem[];
    const int tid = threadIdx.x;
    const int blk = blockIdx.x;
    const int w   = tid >> 5;
    const int l   = tid & 31;

    // ---- stage B = W as bf16 [24 n x 1024 k], swizzled ----
    for (int i = tid; i < 896; i += 128)
        reinterpret_cast<uint4*>(smem + SM_B + 17 * 2048)[i] =
            make_uint4(0u, 0u, 0u, 0u);
    const float4* W4 = reinterpret_cast<const float4*>(W);
    for (int i = tid; i < TT * DD / 4; i += 128) {
        int n = i >> 8, k4 = i & 255;
        uint32_t off = (uint32_t)(n * 2048 + ((k4 * 8) ^ ((n & 7) << 4)));
        *reinterpret_cast<uint2*>(smem + SM_B + off) =
            cvt_f4_bf16x4(__ldg(W4 + i));
    }

    // ---- A staging geometry (warp-private, single 4 KB buffer) ----
    const int lr8 = l >> 4;
    const int q   = l & 15;
    const float4* dq = reinterpret_cast<const float4*>(data);
    const long g0 = (long)(blk * 128 + w * 32 + lr8) * 256 + q;
    char* buf = smem + SM_A + w * 4096;

    float4 raw[16];
    #pragma unroll
    for (int i = 0; i < 16; i++)
        raw[i] = __ldg(dq + g0 + (long)i * 512);

    __syncthreads();   // B ready

    float acc[2][3][4];
    #pragma unroll
    for (int mt = 0; mt < 2; mt++)
        #pragma unroll
        for (int nt = 0; nt < 3; nt++)
            #pragma unroll
            for (int x = 0; x < 4; x++) acc[mt][nt][x] = 0.0f;

    const int rk = l >> 2;
    const int cx = (l & 3) * 4;
    const uint32_t keysh = (uint32_t)rk << 4;
    char* sB = smem + SM_B;

    #pragma unroll 1
    for (int c = 0; c < 16; c++) {
        #pragma unroll
        for (int i = 0; i < 16; i++) {
            uint2 pk = cvt_f4_bf16x4(raw[i]);
            *reinterpret_cast<uint2*>(
                buf + (i * 2 + lr8) * 128 +
                ((q * 8) ^ (((i & 3) * 2 + lr8) << 4))) = pk;
        }
        __syncwarp();

        if (c < 15) {
            #pragma unroll
            for (int i = 0; i < 16; i++)
                raw[i] = __ldg(dq + g0 + (long)i * 512 + (c + 1) * 16);
        }

        #pragma unroll
        for (int ks = 0; ks < 4; ks++) {
            const uint32_t a0o = (uint32_t)(rk * 128) + (((uint32_t)(ks * 32 + cx)) ^ keysh);
            uint32_t aA[2][4];
            #pragma unroll
            for (int mt = 0; mt < 2; mt++) {
                char* bm = buf + mt * 2048;
                aA[mt][0] = *reinterpret_cast<uint32_t*>(bm + a0o);
                aA[mt][1] = *reinterpret_cast<uint32_t*>(bm + a0o + 1024);
                aA[mt][2] = *reinterpret_cast<uint32_t*>(bm + (a0o ^ 16));
                aA[mt][3] = *reinterpret_cast<uint32_t*>(bm + (a0o ^ 16) + 1024);
            }
            #pragma unroll
            for (int nt = 0; nt < 3; nt++) {
                const uint32_t b0o = (uint32_t)((nt * 8 + rk) * 2048) +
                    (((uint32_t)(c * 128 + ks * 32 + cx)) ^ keysh);
                uint32_t bb[2];
                bb[0] = *reinterpret_cast<uint32_t*>(sB + b0o);
                bb[1] = *reinterpret_cast<uint32_t*>(sB + (b0o ^ 16));
                mma16816(acc[0][nt], aA[0], bb);
                mma16816(acc[1][nt], aA[1], bb);
            }
        }
        __syncwarp();
    }

    // ---- D -> smem (stride 26 floats), then per-thread row epilogue ----
    __syncthreads();
    float* sD = reinterpret_cast<float*>(smem + SM_D);
    #pragma unroll
    for (int mt = 0; mt < 2; mt++)
        #pragma unroll
        for (int nt = 0; nt < 3; nt++) {
            int r  = w * 32 + mt * 16 + rk;
            int cb = nt * 8 + (l & 3) * 2;
            *reinterpret_cast<float2*>(sD + r * 26 + cb) =
                make_float2(acc[mt][nt][0], acc[mt][nt][1]);
            *reinterpret_cast<float2*>(sD + (r + 8) * 26 + cb) =
                make_float2(acc[mt][nt][2], acc[mt][nt][3]);
        }
    __syncthreads();

    const int row = blk * 128 + tid;
    const int s   = row & (SS - 1);

    float emv[TT];
    float m = -1e30f;
    #pragma unroll
    for (int t = 0; t < TT; t++) {
        emv[t] = sD[tid * 26 + t] + __ldg(bias + t);
        m = fmaxf(m, emv[t]);
    }
    float e[TT];
    #pragma unroll
    for (int t = 0; t < TT; t++) e[t] = __expf(emv[t] - m);

    float4* o4 = reinterpret_cast<float4*>(g_eem + (size_t)row * EST);
    o4[0] = make_float4(e[0],  e[1],  e[2],  e[3]);
    o4[1] = make_float4(e[4],  e[5],  e[6],  e[7]);
    o4[2] = make_float4(e[8],  e[9],  e[10], e[11]);
    o4[3] = make_float4(e[12], e[13], e[14], e[15]);
    o4[4] = make_float4(e[16], 0.0f,  0.0f,  0.0f);

    int lab = __ldg(labels + row);
    float em_lab = 0.0f;
    #pragma unroll
    for (int t = 0; t < TT; t++) em_lab = (lab == t) ? emv[t] : em_lab;

    float mk = (__ldg(mask + row) != 0) ? 1.0f : 0.0f;
    float contrib;
    if (s == 0) {
        contrib = __ldg(start + lab) + em_lab;
    } else {
        int prev = __ldg(labels + row - 1);
        contrib = mk * (__ldg(trans + prev * TT + lab) + em_lab);
    }
    float msum_t = mk * m;
    int   mcnt_t = (mk > 0.0f) ? 1 : 0;

    const unsigned FULL = 0xffffffffu;
    #pragma unroll
    for (int off = 16; off; off >>= 1) {
        contrib += __shfl_xor_sync(FULL, contrib, off);
        msum_t  += __shfl_xor_sync(FULL, msum_t, off);
        mcnt_t  += __shfl_xor_sync(FULL, mcnt_t, off);
    }
    float* red = reinterpret_cast<float*>(smem + SM_RED);
    if (l == 0) {
        red[w]     = contrib;
        red[4 + w] = msum_t;
        reinterpret_cast<int*>(red)[8 + w] = mcnt_t;
    }
    __syncthreads();
    if (tid == 0) {
        float sc = 0.0f, sm = 0.0f; int cn = 0;
        #pragma unroll
        for (int ww = 0; ww < 4; ww++) {
            sc += red[ww];
            sm += red[4 + ww];
            cn += reinterpret_cast<int*>(red)[8 + ww];
        }
        g_part_score[blk] = sc;
        g_part_msum[blk]  = sm;
        g_part_mcnt[blk]  = cn;
    }
}

// ============================================================
// Kernel 2: CRF forward recurrence (linear domain, lazy renorm)
//   128 blocks x 64 threads, 1 warp/batch. Matvec via smem
//   broadcast (STS + 5 LDS) instead of 17 SHFL broadcasts.
// ============================================================
__global__ void __launch_bounds__(64)
crf_kernel(const float* __restrict__ trans, const float* __restrict__ start,
           const float* __restrict__ endt, const int* __restrict__ mask)
{
    __shared__ __align__(16) float sp[2][2][32];   // [warp][buf][lane]
    const unsigned FULL = 0xffffffffu;
    const int wId = threadIdx.x >> 5;
    const int b = blockIdx.x * 2 + wId;
    const int j = threadIdx.x & 31;
    const bool act = (j < TT);

    float Ecol[TT];
    #pragma unroll
    for (int i = 0; i < TT; i++)
        Ecol[i] = act ? __expf(__ldg(trans + i * TT + j)) : 0.0f;
    float eend = act ? __expf(__ldg(endt + j)) : 0.0f;

    const float* eb = g_eem + (size_t)b * (SS * EST);
    const int4* mb = reinterpret_cast<const int4*>(mask + b * SS);

    float bufA[8], bufB[8];
    int   mA[8],  mB[8];

    #pragma unroll
    for (int d = 0; d < 8; d++)
        bufA[d] = act ? __ldg(eb + d * EST + j) : 0.0f;
    {
        int4 a = __ldg(mb + 0), c = __ldg(mb + 1);
        mA[0]=a.x; mA[1]=a.y; mA[2]=a.z; mA[3]=a.w;
        mA[4]=c.x; mA[5]=c.y; mA[6]=c.z; mA[7]=c.w;
    }

    float p = act ? bufA[0] * __expf(__ldg(start + j)) : 0.0f;
    float C = 0.0f;
    float r  = __shfl_sync(FULL, p, 0);
    float sc = __fdividef(1.0f, r);
    float lr = __logf(r);
    int cur = 0;
    sp[wId][0][j] = p;
    __syncwarp();

    auto step = [&](float eemv, int mkv) {
        if (mkv != 0) {  // warp-uniform
            const float* pv = sp[wId][cur];
            float4 v0 = *reinterpret_cast<const float4*>(pv);
            float4 v1 = *reinterpret_cast<const float4*>(pv + 4);
            float4 v2 = *reinterpret_cast<const float4*>(pv + 8);
            float4 v3 = *reinterpret_cast<const float4*>(pv + 12);
            float v16 = pv[16];
            float a0 = v0.x * Ecol[0];
            float a1 = v0.y * Ecol[1];
            float a2 = v0.z * Ecol[2];
            float a3 = v0.w * Ecol[3];
            a0 = fmaf(v1.x, Ecol[4],  a0);
            a1 = fmaf(v1.y, Ecol[5],  a1);
            a2 = fmaf(v1.z, Ecol[6],  a2);
            a3 = fmaf(v1.w, Ecol[7],  a3);
            a0 = fmaf(v2.x, Ecol[8],  a0);
            a1 = fmaf(v2.y, Ecol[9],  a1);
            a2 = fmaf(v2.z, Ecol[10], a2);
            a3 = fmaf(v2.w, Ecol[11], a3);
            a0 = fmaf(v3.x, Ecol[12], a0);
            a1 = fmaf(v3.y, Ecol[13], a1);
            a2 = fmaf(v3.z, Ecol[14], a2);
            a3 = fmaf(v3.w, Ecol[15], a3);
            a0 = fmaf(v16,  Ecol[16], a0);
            float q = (a0 + a1) + (a2 + a3);
            p = q * (eemv * sc);   // lazy scale from previous step
            C += lr;
            cur ^= 1;
            sp[wId][cur][j] = p;
            r = __shfl_sync(FULL, p, 0);
            __syncwarp();
            sc = __fdividef(1.0f, r);
            lr = __logf(r);
        }
    };

    #define PREFETCH(cidx, BUF, MARR)                                          \
        do {                                                                    \
            _Pragma("unroll")                                                   \
            for (int d = 0; d < 8; d++)                                         \
                BUF[d] = act ? __ldg(eb + ((cidx) * 8 + d) * EST + j) : 0.0f;   \
            int4 _a = __ldg(mb + 2 * (cidx)), _c = __ldg(mb + 2 * (cidx) + 1);  \
            MARR[0]=_a.x; MARR[1]=_a.y; MARR[2]=_a.z; MARR[3]=_a.w;             \
            MARR[4]=_c.x; MARR[5]=_c.y; MARR[6]=_c.z; MARR[7]=_c.w;             \
        } while (0)

    #define PROCESS(BUF, MARR)                                                  \
        do {                                                                    \
            _Pragma("unroll")                                                   \
            for (int d = 0; d < 8; d++) step(BUF[d], MARR[d]);                  \
        } while (0)

    PREFETCH(1, bufB, mB);
    #pragma unroll
    for (int d = 1; d < 8; d++) step(bufA[d], mA[d]);

    for (int cc = 1; cc < 63; cc += 2) {
        PREFETCH(cc + 1, bufA, mA);
        PROCESS(bufB, mB);
        PREFETCH(cc + 2, bufB, mB);
        PROCESS(bufA, mA);
    }
    PROCESS(bufB, mB);

    float term = p * eend;
    #pragma unroll
    for (int off = 16; off; off >>= 1)
        term += __shfl_xor_sync(FULL, term, off);
    if (j == 0) g_denom[b] = C + __logf(term);

    #undef PREFETCH
    #undef PROCESS
}

// ============================================================
// Kernel 3: finalize  out = -mean(score - denom)
// ============================================================
__global__ void __launch_bounds__(256)
fin_kernel(const int* __restrict__ labels, const float* __restrict__ endt,
           float* __restrict__ out)
{
    __shared__ float sred[256];
    int b = threadIdx.x;
    int cnt = 0;
    float psc = 0.0f, pms = 0.0f;
    #pragma unroll
    for (int k = 0; k < 4; k++) {
        cnt += g_part_mcnt[4 * b + k];
        psc += g_part_score[4 * b + k];
        pms += g_part_msum[4 * b + k];
    }
    int lt = __ldg(labels + b * SS + (cnt - 1));
    float score = psc + __ldg(endt + lt);
    float denom = g_denom[b] + pms;
    sred[b] = score - denom;
    __syncthreads();
    #pragma unroll
    for (int off = 128; off; off >>= 1) {
        if (b < off) sred[b] += sred[b + off];
        __syncthreads();
    }
    if (b == 0) out[0] = -sred[0] * (1.0f / BB);
}

// ============================================================
extern "C" void kernel_launch(void* const* d_in, const int* in_sizes, int n_in,
                              void* d_out, int out_size)
{
    const float* data   = (const float*)d_in[0];
    const int*   labels = (const int*)d_in[1];
    const int*   mask   = (const int*)d_in[2];
    const float* W      = (const float*)d_in[3];
    const float* bias   = (const float*)d_in[4];
    const float* start  = (const float*)d_in[5];
    const float* endt   = (const float*)d_in[6];
    const float* trans  = (const float*)d_in[7];

    cudaFuncSetAttribute(emis_kernel,
                         cudaFuncAttributeMaxDynamicSharedMemorySize, SM_TOT);

    emis_kernel<<<1024, 128, SM_TOT>>>(data, labels, mask, W, bias, start, trans);
    crf_kernel<<<BB / 2, 64>>>(trans, start, endt, mask);
    fin_kernel<<<1, 256>>>(labels, endt, (float*)d_out);
}

// round 14
// speedup vs baseline: 1.7008x; 1.1002x over previous
#include <cuda_runtime.h>
#include <cuda_bf16.h>
#include <cstdint>

#define BB 256
#define SS 512
#define DD 1024
#define TT 17
#define EST 20   // padded eem row stride (16B-aligned rows)

// ---------------- device scratch (no allocations allowed) ----------------
__device__ float g_eem[(size_t)BB * SS * EST];  // exp(em - rowmax), 10.5 MB
__device__ float g_part_score[1024];            // per-CTA numerator partials
__device__ float g_part_msum[1024];             // per-CTA sum of masked row-maxes
__device__ int   g_part_mcnt[1024];             // per-CTA mask counts
__device__ float g_denom[BB];                   // log partition minus msum offset

// ---------------- smem layout (bytes) ----------------
#define SM_B    0                       // W bf16: 24 n-rows x 1024 k = 48 KB
#define SM_A    49152                   // 4 warps x 1 buf x 4 KB = 16 KB
#define SM_D    SM_A                    // D reuse: 128 x 26 fp32 = 13312 B
#define SM_RED  (SM_A + 16384)          // 65536
#define SM_TOT  (SM_RED + 64)           // 65600

__device__ __forceinline__ uint2 cvt_f4_bf16x4(float4 f) {
    uint2 r;
    // low 16 bits = earlier k element
    asm("cvt.rn.bf16x2.f32 %0, %1, %2;" : "=r"(r.x) : "f"(f.y), "f"(f.x));
    asm("cvt.rn.bf16x2.f32 %0, %1, %2;" : "=r"(r.y) : "f"(f.w), "f"(f.z));
    return r;
}

__device__ __forceinline__ void mma16816(float* d, const uint32_t* a,
                                         const uint32_t* b) {
    asm volatile(
        "mma.sync.aligned.m16n8k16.row.col.f32.bf16.bf16.f32 "
        "{%0,%1,%2,%3}, {%4,%5,%6,%7}, {%8,%9}, {%0,%1,%2,%3};"
        : "+f"(d[0]), "+f"(d[1]), "+f"(d[2]), "+f"(d[3])
        : "r"(a[0]), "r"(a[1]), "r"(a[2]), "r"(a[3]), "r"(b[0]), "r"(b[1]));
}

// ============================================================
// Kernel 1: HMMA emissions GEMM + eem/rowmax + numerator partials
//   1024 CTAs x 128 threads, 3 CTAs/SM (unchanged, R11 measured-best)
// ============================================================
__global__ void __launch_bounds__(128, 3)
emis_kernel(const float* __restrict__ data, const int* __restrict__ labels,
            const int* __restrict__ mask, const float* __restrict__ W,
            const float* __restrict__ bias, const float* __restrict__ start,
            const float* __restrict__ trans)
{
    extern __shared__ char smem[];
    const int tid = threadIdx.x;
    const int blk = blockIdx.x;
    const int w   = tid >> 5;
    const int l   = tid & 31;

    // ---- stage B = W as bf16 [24 n x 1024 k], swizzled ----
    for (int i = tid; i < 896; i += 128)
        reinterpret_cast<uint4*>(smem + SM_B + 17 * 2048)[i] =
            make_uint4(0u, 0u, 0u, 0u);
    const float4* W4 = reinterpret_cast<const float4*>(W);
    for (int i = tid; i < TT * DD / 4; i += 128) {
        int n = i >> 8, k4 = i & 255;
        uint32_t off = (uint32_t)(n * 2048 + ((k4 * 8) ^ ((n & 7) << 4)));
        *reinterpret_cast<uint2*>(smem + SM_B + off) =
            cvt_f4_bf16x4(__ldg(W4 + i));
    }

    // ---- A staging geometry (warp-private, single 4 KB buffer) ----
    const int lr8 = l >> 4;
    const int q   = l & 15;
    const float4* dq = reinterpret_cast<const float4*>(data);
    const long g0 = (long)(blk * 128 + w * 32 + lr8) * 256 + q;
    char* buf = smem + SM_A + w * 4096;

    float4 raw[16];
    #pragma unroll
    for (int i = 0; i < 16; i++)
        raw[i] = __ldg(dq + g0 + (long)i * 512);

    __syncthreads();   // B ready

    float acc[2][3][4];
    #pragma unroll
    for (int mt = 0; mt < 2; mt++)
        #pragma unroll
        for (int nt = 0; nt < 3; nt++)
            #pragma unroll
            for (int x = 0; x < 4; x++) acc[mt][nt][x] = 0.0f;

    const int rk = l >> 2;
    const int cx = (l & 3) * 4;
    const uint32_t keysh = (uint32_t)rk << 4;
    char* sB = smem + SM_B;

    #pragma unroll 1
    for (int c = 0; c < 16; c++) {
        #pragma unroll
        for (int i = 0; i < 16; i++) {
            uint2 pk = cvt_f4_bf16x4(raw[i]);
            *reinterpret_cast<uint2*>(
                buf + (i * 2 + lr8) * 128 +
                ((q * 8) ^ (((i & 3) * 2 + lr8) << 4))) = pk;
        }
        __syncwarp();

        if (c < 15) {
            #pragma unroll
            for (int i = 0; i < 16; i++)
                raw[i] = __ldg(dq + g0 + (long)i * 512 + (c + 1) * 16);
        }

        #pragma unroll
        for (int ks = 0; ks < 4; ks++) {
            const uint32_t a0o = (uint32_t)(rk * 128) + (((uint32_t)(ks * 32 + cx)) ^ keysh);
            uint32_t aA[2][4];
            #pragma unroll
            for (int mt = 0; mt < 2; mt++) {
                char* bm = buf + mt * 2048;
                aA[mt][0] = *reinterpret_cast<uint32_t*>(bm + a0o);
                aA[mt][1] = *reinterpret_cast<uint32_t*>(bm + a0o + 1024);
                aA[mt][2] = *reinterpret_cast<uint32_t*>(bm + (a0o ^ 16));
                aA[mt][3] = *reinterpret_cast<uint32_t*>(bm + (a0o ^ 16) + 1024);
            }
            #pragma unroll
            for (int nt = 0; nt < 3; nt++) {
                const uint32_t b0o = (uint32_t)((nt * 8 + rk) * 2048) +
                    (((uint32_t)(c * 128 + ks * 32 + cx)) ^ keysh);
                uint32_t bb[2];
                bb[0] = *reinterpret_cast<uint32_t*>(sB + b0o);
                bb[1] = *reinterpret_cast<uint32_t*>(sB + (b0o ^ 16));
                mma16816(acc[0][nt], aA[0], bb);
                mma16816(acc[1][nt], aA[1], bb);
            }
        }
        __syncwarp();
    }

    // ---- D -> smem (stride 26 floats), then per-thread row epilogue ----
    __syncthreads();
    float* sD = reinterpret_cast<float*>(smem + SM_D);
    #pragma unroll
    for (int mt = 0; mt < 2; mt++)
        #pragma unroll
        for (int nt = 0; nt < 3; nt++) {
            int r  = w * 32 + mt * 16 + rk;
            int cb = nt * 8 + (l & 3) * 2;
            *reinterpret_cast<float2*>(sD + r * 26 + cb) =
                make_float2(acc[mt][nt][0], acc[mt][nt][1]);
            *reinterpret_cast<float2*>(sD + (r + 8) * 26 + cb) =
                make_float2(acc[mt][nt][2], acc[mt][nt][3]);
        }
    __syncthreads();

    const int row = blk * 128 + tid;
    const int s   = row & (SS - 1);

    float emv[TT];
    float m = -1e30f;
    #pragma unroll
    for (int t = 0; t < TT; t++) {
        emv[t] = sD[tid * 26 + t] + __ldg(bias + t);
        m = fmaxf(m, emv[t]);
    }
    float e[TT];
    #pragma unroll
    for (int t = 0; t < TT; t++) e[t] = __expf(emv[t] - m);

    float4* o4 = reinterpret_cast<float4*>(g_eem + (size_t)row * EST);
    o4[0] = make_float4(e[0],  e[1],  e[2],  e[3]);
    o4[1] = make_float4(e[4],  e[5],  e[6],  e[7]);
    o4[2] = make_float4(e[8],  e[9],  e[10], e[11]);
    o4[3] = make_float4(e[12], e[13], e[14], e[15]);
    o4[4] = make_float4(e[16], 0.0f,  0.0f,  0.0f);

    int lab = __ldg(labels + row);
    float em_lab = 0.0f;
    #pragma unroll
    for (int t = 0; t < TT; t++) em_lab = (lab == t) ? emv[t] : em_lab;

    float mk = (__ldg(mask + row) != 0) ? 1.0f : 0.0f;
    float contrib;
    if (s == 0) {
        contrib = __ldg(start + lab) + em_lab;
    } else {
        int prev = __ldg(labels + row - 1);
        contrib = mk * (__ldg(trans + prev * TT + lab) + em_lab);
    }
    float msum_t = mk * m;
    int   mcnt_t = (mk > 0.0f) ? 1 : 0;

    const unsigned FULL = 0xffffffffu;
    #pragma unroll
    for (int off = 16; off; off >>= 1) {
        contrib += __shfl_xor_sync(FULL, contrib, off);
        msum_t  += __shfl_xor_sync(FULL, msum_t, off);
        mcnt_t  += __shfl_xor_sync(FULL, mcnt_t, off);
    }
    float* red = reinterpret_cast<float*>(smem + SM_RED);
    if (l == 0) {
        red[w]     = contrib;
        red[4 + w] = msum_t;
        reinterpret_cast<int*>(red)[8 + w] = mcnt_t;
    }
    __syncthreads();
    if (tid == 0) {
        float sc = 0.0f, sm = 0.0f; int cn = 0;
        #pragma unroll
        for (int ww = 0; ww < 4; ww++) {
            sc += red[ww];
            sm += red[4 + ww];
            cn += reinterpret_cast<int*>(red)[8 + ww];
        }
        g_part_score[blk] = sc;
        g_part_msum[blk]  = sm;
        g_part_mcnt[blk]  = cn;
    }
}

// ============================================================
// Kernel 2: CRF forward recurrence (linear domain)
//   Renorm hoisted OUT of the step: once per 8-step chunk.
//   Per-step body: guard + 17 shfl/FMA + tree + 1 mul.
//   128 blocks x 64 threads, 1 warp per batch (R4-proven skeleton).
// ============================================================
__global__ void __launch_bounds__(64)
crf_kernel(const float* __restrict__ trans, const float* __restrict__ start,
           const float* __restrict__ endt, const int* __restrict__ mask)
{
    const unsigned FULL = 0xffffffffu;
    int b = blockIdx.x * 2 + (threadIdx.x >> 5);
    int j = threadIdx.x & 31;
    bool act = (j < TT);

    float Ecol[TT];
    #pragma unroll
    for (int i = 0; i < TT; i++)
        Ecol[i] = act ? __expf(__ldg(trans + i * TT + j)) : 0.0f;
    float eend = act ? __expf(__ldg(endt + j)) : 0.0f;

    const float* eb = g_eem + (size_t)b * (SS * EST);
    const int4* mb = reinterpret_cast<const int4*>(mask + b * SS);

    float bufA[8], bufB[8];
    int   mA[8],  mB[8];

    #pragma unroll
    for (int d = 0; d < 8; d++)
        bufA[d] = act ? __ldg(eb + d * EST + j) : 0.0f;
    {
        int4 a = __ldg(mb + 0), c = __ldg(mb + 1);
        mA[0]=a.x; mA[1]=a.y; mA[2]=a.z; mA[3]=a.w;
        mA[4]=c.x; mA[5]=c.y; mA[6]=c.z; mA[7]=c.w;
    }

    float p = act ? bufA[0] * __expf(__ldg(start + j)) : 0.0f;
    float C = 0.0f;

    // lean step: no per-step renorm (range bounded within a chunk)
    auto step = [&](float eemv, int mkv) {
        if (mkv != 0) {  // warp-uniform
            float a[4] = {0.f, 0.f, 0.f, 0.f};
            #pragma unroll
            for (int i = 0; i < TT; i++)
                a[i & 3] = fmaf(__shfl_sync(FULL, p, i), Ecol[i], a[i & 3]);
            p = ((a[0] + a[1]) + (a[2] + a[3])) * eemv;
        }
    };

    // once-per-chunk renorm: p /= p0, C += log p0 (invariant-preserving)
    auto renorm = [&]() {
        float r = __shfl_sync(FULL, p, 0);
        p *= __fdividef(1.0f, r);
        C += __logf(r);
    };

    #define PREFETCH(cidx, BUF, MARR)                                          \
        do {                                                                    \
            _Pragma("unroll")                                                   \
            for (int d = 0; d < 8; d++)                                         \
                BUF[d] = act ? __ldg(eb + ((cidx) * 8 + d) * EST + j) : 0.0f;   \
            int4 _a = __ldg(mb + 2 * (cidx)), _c = __ldg(mb + 2 * (cidx) + 1);  \
            MARR[0]=_a.x; MARR[1]=_a.y; MARR[2]=_a.z; MARR[3]=_a.w;             \
            MARR[4]=_c.x; MARR[5]=_c.y; MARR[6]=_c.z; MARR[7]=_c.w;             \
        } while (0)

    #define PROCESS(BUF, MARR)                                                  \
        do {                                                                    \
            _Pragma("unroll")                                                   \
            for (int d = 0; d < 8; d++) step(BUF[d], MARR[d]);                  \
            renorm();                                                           \
        } while (0)

    // prefetch chunk 1, process chunk 0 steps 1..7
    PREFETCH(1, bufB, mB);
    #pragma unroll
    for (int d = 1; d < 8; d++) step(bufA[d], mA[d]);
    renorm();

    // main: chunks 1..62 double-buffered, chunk 63 tail
    for (int cc = 1; cc < 63; cc += 2) {
        PREFETCH(cc + 1, bufA, mA);
        PROCESS(bufB, mB);
        PREFETCH(cc + 2, bufB, mB);
        PROCESS(bufA, mA);
    }
    PROCESS(bufB, mB);

    // denom (minus msum offset) = C + log(sum_j p_j * exp(end_j))
    float term = p * eend;
    #pragma unroll
    for (int off = 16; off; off >>= 1)
        term += __shfl_xor_sync(FULL, term, off);
    if (j == 0) g_denom[b] = C + __logf(term);

    #undef PREFETCH
    #undef PROCESS
}

// ============================================================
// Kernel 3: finalize  out = -mean(score - denom)
// ============================================================
__global__ void __launch_bounds__(256)
fin_kernel(const int* __restrict__ labels, const float* __restrict__ endt,
           float* __restrict__ out)
{
    __shared__ float sred[256];
    int b = threadIdx.x;
    int cnt = 0;
    float psc = 0.0f, pms = 0.0f;
    #pragma unroll
    for (int k = 0; k < 4; k++) {
        cnt += g_part_mcnt[4 * b + k];
        psc += g_part_score[4 * b + k];
        pms += g_part_msum[4 * b + k];
    }
    int lt = __ldg(labels + b * SS + (cnt - 1));
    float score = psc + __ldg(endt + lt);
    float denom = g_denom[b] + pms;
    sred[b] = score - denom;
    __syncthreads();
    #pragma unroll
    for (int off = 128; off; off >>= 1) {
        if (b < off) sred[b] += sred[b + off];
        __syncthreads();
    }
    if (b == 0) out[0] = -sred[0] * (1.0f / BB);
}

// ============================================================
extern "C" void kernel_launch(void* const* d_in, const int* in_sizes, int n_in,
                              void* d_out, int out_size)
{
    const float* data   = (const float*)d_in[0];
    const int*   labels = (const int*)d_in[1];
    const int*   mask   = (const int*)d_in[2];
    const float* W      = (const float*)d_in[3];
    const float* bias   = (const float*)d_in[4];
    const float* start  = (const float*)d_in[5];
    const float* endt   = (const float*)d_in[6];
    const float* trans  = (const float*)d_in[7];

    cudaFuncSetAttribute(emis_kernel,
                         cudaFuncAttributeMaxDynamicSharedMemorySize, SM_TOT);

    emis_kernel<<<1024, 128, SM_TOT>>>(data, labels, mask, W, bias, start, trans);
    crf_kernel<<<BB / 2, 64>>>(trans, start, endt, mask);
    fin_kernel<<<1, 256>>>(labels, endt, (float*)d_out);
}